// round 17
// baseline (speedup 1.0000x reference)
#include <cuda_runtime.h>
#include <cuda_fp16.h>
#include <mma.h>
using namespace nvcuda;

#define N_NODES 100000
#define N_EDGES 1600000
#define NBLK_SCAN 98   // ceil(100000/1024)

// BM=64 GEMM smem layout
#define OFF_B   17408                     // sA: 64 x 136 halfs
#define OFF_SW  17408                     // s_w aliases sB region (dead until W load)
#define OFF_SSRC (17408 + 4224)
#define OFF_AL  52224                     // after sA+sB
#define SMEM_GEMM (52224 + 1024)

#define CSR_BLOCKS 1563                   // ceil(400000/256) edge-quad blocks
#define GEMM_BLOCKS 1563                  // ceil(100000/64)
#define GEMM_HALF_A 782                   // gemm1 rows 0..50047
#define GEMM_HALF_B 781                   // gemm1 rows 50048..99999

// ---------------- scratch (allocation-free: __device__ globals) ----------------
__device__ __align__(16) __half g_featA[100096 * 128];   // double-buffered fp16 features
__device__ __align__(16) __half g_featB[100096 * 128];
__device__ __align__(16) __half g_Wh[3][128 * 128];      // fp16 weights
__device__ __align__(16) float g_elA[N_NODES * 4];
__device__ __align__(16) float g_erA[N_NODES * 4];
__device__ __align__(16) float g_elB[N_NODES * 4];
__device__ __align__(16) float g_erB[N_NODES * 4];
__device__ int   g_rowptr[N_NODES + 1];
__device__ int   g_cursor[N_NODES];
__device__ int   g_deg[N_NODES];
__device__ int   g_esrc[N_EDGES];
__device__ int   g_bsum[128];
__device__ float g_pooled[128];

__device__ __forceinline__ float lrelu(float x) { return x > 0.f ? x : 0.2f * x; }

// ---------------- prep: convert W + zero degree counts + pooled ----------------
__global__ void prep_kernel(const float* __restrict__ W1, const float* __restrict__ W2,
                            const float* __restrict__ W3) {
    int i = blockIdx.x * blockDim.x + threadIdx.x;
    if (i < 128 * 128) {
        g_Wh[0][i] = __float2half_rn(W1[i]);
        g_Wh[1][i] = __float2half_rn(W2[i]);
        g_Wh[2][i] = __float2half_rn(W3[i]);
    }
    if (i < N_NODES) g_deg[i] = 0;
    if (i < 128)     g_pooled[i] = 0.f;
}

__global__ void scan1_kernel() {          // NBLK_SCAN blocks x 1024
    __shared__ int wsum[32];
    int t = threadIdx.x, lane = t & 31, w = t >> 5;
    int i = blockIdx.x * 1024 + t;
    int v = (i < N_NODES) ? g_deg[i] : 0;
    int x = v;
#pragma unroll
    for (int o = 1; o < 32; o <<= 1) {
        int y = __shfl_up_sync(0xffffffffu, x, o);
        if (lane >= o) x += y;
    }
    if (lane == 31) wsum[w] = x;
    __syncthreads();
    if (w == 0) {
        int sv = wsum[lane];
#pragma unroll
        for (int o = 1; o < 32; o <<= 1) {
            int y = __shfl_up_sync(0xffffffffu, sv, o);
            if (lane >= o) sv += y;
        }
        wsum[lane] = sv;
    }
    __syncthreads();
    int incl = x + (w > 0 ? wsum[w - 1] : 0);
    if (i < N_NODES) g_rowptr[i + 1] = incl;
    if (t == 1023)   g_bsum[blockIdx.x] = incl;
}

// scan3 re-derives the 98-entry block-prefix in smem (absorbs old scan2)
__global__ void scan3_kernel() {
    __shared__ int s[128];
    int t = threadIdx.x;
    if (t < 128) s[t] = (t < NBLK_SCAN) ? g_bsum[t] : 0;
    __syncthreads();
    for (int o = 1; o < 128; o <<= 1) {
        int y = (t < 128 && t >= o) ? s[t - o] : 0;
        __syncthreads();
        if (t < 128) s[t] += y;
        __syncthreads();
    }
    int i = blockIdx.x * blockDim.x + t;
    if (i < N_NODES) {
        int b = i >> 10;
        int off = (b > 0) ? s[b - 1] : 0;
        int r = g_rowptr[i + 1] + off;
        g_rowptr[i + 1] = r;
        g_cursor[i] = r - g_deg[i];
        if (i == 0) g_rowptr[0] = 0;
    }
}

// ---------------- shared GEMM core (BM=64), called with sA filled ----------------
__device__ __forceinline__ void gemm_core(char* sbuf, int which, int rb,
                                          __half* featOut, float* elOut, float* erOut) {
    __half* sA  = reinterpret_cast<__half*>(sbuf);
    __half* sB  = reinterpret_cast<__half*>(sbuf + OFF_B);
    float*  sC  = reinterpret_cast<float*>(sbuf);     // 8 x (16 x 68) f32
    float*  sal = reinterpret_cast<float*>(sbuf + OFF_AL);
    float*  sar = sal + 128;
    int t = threadIdx.x, w = t >> 5, lane = t & 31;
    int wr = w & 3, wc = w >> 2;

    const __half* Wh = g_Wh[which];
    for (int i = t; i < 2048; i += 256) {
        int r = i >> 4, s = i & 15;
        *reinterpret_cast<uint4*>(&sB[r * 136 + s * 8]) =
            *reinterpret_cast<const uint4*>(&Wh[r * 128 + s * 8]);
    }
    __syncthreads();

    wmma::fragment<wmma::matrix_a, 16, 16, 16, __half, wmma::row_major> af;
    wmma::fragment<wmma::matrix_b, 16, 16, 16, __half, wmma::row_major> bf;
    wmma::fragment<wmma::accumulator, 16, 16, 16, float> acc[4];
#pragma unroll
    for (int i = 0; i < 4; i++) wmma::fill_fragment(acc[i], 0.f);

#pragma unroll
    for (int k = 0; k < 8; k++) {
        wmma::load_matrix_sync(af, sA + (wr * 16) * 136 + k * 16, 136);
#pragma unroll
        for (int i = 0; i < 4; i++) {
            wmma::load_matrix_sync(bf, sB + (k * 16) * 136 + (wc * 64 + i * 16), 136);
            wmma::mma_sync(acc[i], af, bf, acc[i]);
        }
    }
    __syncthreads();   // all warps done reading sA/sB; sC aliases them

    float* myC = sC + w * (16 * 68);
#pragma unroll
    for (int i = 0; i < 4; i++)
        wmma::store_matrix_sync(myC + i * 16, acc[i], 68, wmma::mem_row_major);
    __syncwarp();

    int r  = lane & 15, hi = lane >> 4;
    int h  = 2 * wc + hi;
    int row = rb + wr * 16 + r;
    const float* rowC = myC + r * 68 + hi * 32;
    if (row < N_NODES) {
        float pl = 0.f, pr = 0.f;
        uint4 packo[4];
        unsigned* pw = reinterpret_cast<unsigned*>(packo);
#pragma unroll
        for (int c4 = 0; c4 < 8; c4++) {
            float4 v = *reinterpret_cast<const float4*>(&rowC[c4 * 4]);
            float4 a = *reinterpret_cast<float4*>(&sal[h * 32 + c4 * 4]);
            float4 b = *reinterpret_cast<float4*>(&sar[h * 32 + c4 * 4]);
            pl += v.x * a.x + v.y * a.y + v.z * a.z + v.w * a.w;
            pr += v.x * b.x + v.y * b.y + v.z * b.z + v.w * b.w;
            __half2 p0 = __float22half2_rn(make_float2(v.x, v.y));
            __half2 p1 = __float22half2_rn(make_float2(v.z, v.w));
            pw[c4 * 2 + 0] = *reinterpret_cast<unsigned*>(&p0);
            pw[c4 * 2 + 1] = *reinterpret_cast<unsigned*>(&p1);
        }
        uint4* dstp = reinterpret_cast<uint4*>(featOut) + (size_t)row * 16 + h * 4;
        dstp[0] = packo[0]; dstp[1] = packo[1];
        dstp[2] = packo[2]; dstp[3] = packo[3];
        elOut[row * 4 + h] = pl;
        erOut[row * 4 + h] = pr;
    }
}

// gemm1 tile body: convert fp32 x in-flight into sA, then core
__device__ __forceinline__ void gemm1_body(char* sbuf, const float* xin, int gid,
                                           const float* al, const float* ar) {
    __half* sA  = reinterpret_cast<__half*>(sbuf);
    float*  sal = reinterpret_cast<float*>(sbuf + OFF_AL);
    float*  sar = sal + 128;
    int t = threadIdx.x;
    int rb = gid * 64;

    if (t < 128) sal[t] = __ldg(&al[t]);
    else         sar[t - 128] = __ldg(&ar[t - 128]);

    for (int i = t; i < 1024; i += 256) {
        int r = i >> 4, s = i & 15;
        float4 a = make_float4(0.f, 0.f, 0.f, 0.f), b = a;
        if (rb + r < N_NODES) {
            const float4* xr =
                reinterpret_cast<const float4*>(xin + (size_t)(rb + r) * 128 + s * 8);
            a = __ldg(xr); b = __ldg(xr + 1);
        }
        __half2 h0 = __float22half2_rn(make_float2(a.x, a.y));
        __half2 h1 = __float22half2_rn(make_float2(a.z, a.w));
        __half2 h2 = __float22half2_rn(make_float2(b.x, b.y));
        __half2 h3 = __float22half2_rn(make_float2(b.z, b.w));
        uint4 u;
        u.x = *reinterpret_cast<unsigned*>(&h0);
        u.y = *reinterpret_cast<unsigned*>(&h1);
        u.z = *reinterpret_cast<unsigned*>(&h2);
        u.w = *reinterpret_cast<unsigned*>(&h3);
        *reinterpret_cast<uint4*>(&sA[r * 136 + s * 8]) = u;
    }
    __syncthreads();
    gemm_core(sbuf, 0, rb, g_featA, g_elA, g_erA);
}

// ---------------- k1: count (atomic) interleaved with gemm1 half A ----------------
// blocks [0,1564): even -> count cid=b>>1, odd -> gemm gid=b>>1
// blocks [1564,2345): count cid = 782 + (b-1564)
__global__ void __launch_bounds__(256, 4)
count_gemm1_kernel(const int* __restrict__ dst, const float* __restrict__ xin,
                   const float* __restrict__ al, const float* __restrict__ ar) {
    extern __shared__ __align__(16) char sbuf[];
    int b = blockIdx.x;
    int cid = -1, gid = -1;
    if (b < 2 * GEMM_HALF_A) {
        if (b & 1) gid = b >> 1; else cid = b >> 1;
    } else {
        cid = GEMM_HALF_A + (b - 2 * GEMM_HALF_A);
    }
    if (cid >= 0) {
        int e4 = cid * 256 + threadIdx.x;
        if (e4 < N_EDGES / 4) {
            int4 d = __ldg(&reinterpret_cast<const int4*>(dst)[e4]);
            atomicAdd(&g_deg[d.x], 1);
            atomicAdd(&g_deg[d.y], 1);
            atomicAdd(&g_deg[d.z], 1);
            atomicAdd(&g_deg[d.w], 1);
        }
        return;
    }
    gemm1_body(sbuf, xin, gid, al, ar);
}

// ---------------- k2: fill (atomic scatter) interleaved with gemm1 half B ----------
// blocks [0,1562): even -> fill cid=b>>1, odd -> gemm gid=782+(b>>1)
// blocks [1562,2344): fill cid = 781 + (b-1562)
__global__ void __launch_bounds__(256, 4)
fill_gemm1_kernel(const int* __restrict__ src, const int* __restrict__ dst,
                  const float* __restrict__ xin,
                  const float* __restrict__ al, const float* __restrict__ ar) {
    extern __shared__ __align__(16) char sbuf[];
    int b = blockIdx.x;
    int cid = -1, gid = -1;
    if (b < 2 * GEMM_HALF_B) {
        if (b & 1) gid = GEMM_HALF_A + (b >> 1); else cid = b >> 1;
    } else {
        cid = GEMM_HALF_B + (b - 2 * GEMM_HALF_B);
    }
    if (cid >= 0) {
        int e4 = cid * 256 + threadIdx.x;
        if (e4 < N_EDGES / 4) {
            int4 s = __ldg(&reinterpret_cast<const int4*>(src)[e4]);
            int4 d = __ldg(&reinterpret_cast<const int4*>(dst)[e4]);
            g_esrc[atomicAdd(&g_cursor[d.x], 1)] = s.x;
            g_esrc[atomicAdd(&g_cursor[d.y], 1)] = s.y;
            g_esrc[atomicAdd(&g_cursor[d.z], 1)] = s.z;
            g_esrc[atomicAdd(&g_cursor[d.w], 1)] = s.w;
        }
        return;
    }
    gemm1_body(sbuf, xin, gid, al, ar);
}

// ---------------- fused: aggregate(prev layer) into smem act -> GEMM next layer ----
__global__ void __launch_bounds__(256, 4)
fused_agg_gemm_kernel(int dir, int whichW,
                      const float* __restrict__ al, const float* __restrict__ ar) {
    extern __shared__ __align__(16) char sbuf[];
    __half* sA   = reinterpret_cast<__half*>(sbuf);
    float*  s_w  = reinterpret_cast<float*>(sbuf + OFF_SW);     // [8][4][33]
    int*    s_src= reinterpret_cast<int*>(sbuf + OFF_SSRC);     // [8][32]
    float*  sal  = reinterpret_cast<float*>(sbuf + OFF_AL);
    float*  sar  = sal + 128;

    const uint4*  featIn = reinterpret_cast<const uint4*>(dir ? g_featB : g_featA);
    const float4* elIn   = reinterpret_cast<const float4*>(dir ? g_elB : g_elA);
    const float4* erIn   = reinterpret_cast<const float4*>(dir ? g_erB : g_erA);
    __half* featOut = dir ? g_featA : g_featB;
    float*  elOut   = dir ? g_elA : g_elB;
    float*  erOut   = dir ? g_erA : g_erB;

    int t = threadIdx.x, w = t >> 5, lane = t & 31;
    int rb = blockIdx.x * 64;
    int sub = lane & 15, hf = lane >> 4;
    int hh  = sub >> 2;

    if (t < 128) sal[t] = __ldg(&al[t]);
    else         sar[t - 128] = __ldg(&ar[t - 128]);

    for (int it = 0; it < 8; it++) {
        int node = rb + it * 8 + w;
        float acc8[8];
#pragma unroll
        for (int i = 0; i < 8; i++) acc8[i] = 0.f;
        float q0 = 0.f, q1 = 0.f, q2 = 0.f, q3 = 0.f;
        int s0 = 0, deg = 0;
        if (node < N_NODES) {
            s0 = g_rowptr[node];
            deg = g_rowptr[node + 1] - s0;
        }
        if (deg > 0) {
            float4 erd = erIn[node];
            for (int base = 0; base < deg; base += 32) {
                int idx = base + lane;
                int s = 0;
                float w0 = 0.f, w1 = 0.f, w2 = 0.f, w3 = 0.f;
                if (idx < deg) {
                    s = __ldg(&g_esrc[s0 + idx]);
                    float4 ev = __ldg(&elIn[s]);
                    w0 = __expf(lrelu(ev.x + erd.x));
                    w1 = __expf(lrelu(ev.y + erd.y));
                    w2 = __expf(lrelu(ev.z + erd.z));
                    w3 = __expf(lrelu(ev.w + erd.w));
                    q0 += w0; q1 += w1; q2 += w2; q3 += w3;
                }
                __syncwarp();
                s_src[w * 32 + lane] = s;
                s_w[(w * 4 + 0) * 33 + lane] = w0;
                s_w[(w * 4 + 1) * 33 + lane] = w1;
                s_w[(w * 4 + 2) * 33 + lane] = w2;
                s_w[(w * 4 + 3) * 33 + lane] = w3;
                __syncwarp();
                int cnt = min(32, deg - base);
#pragma unroll 4
                for (int j = 0; j < cnt; j += 2) {
                    int jj = j + hf;
                    int   sj = 0;
                    float aa = 0.f;
                    if (jj < cnt) {
                        sj = s_src[w * 32 + jj];
                        aa = s_w[(w * 4 + hh) * 33 + jj];
                    }
                    uint4 fr = __ldg(&featIn[(size_t)sj * 16 + sub]);
                    float2 f0 = __half22float2(*reinterpret_cast<__half2*>(&fr.x));
                    float2 f1 = __half22float2(*reinterpret_cast<__half2*>(&fr.y));
                    float2 f2 = __half22float2(*reinterpret_cast<__half2*>(&fr.z));
                    float2 f3 = __half22float2(*reinterpret_cast<__half2*>(&fr.w));
                    acc8[0] += f0.x * aa; acc8[1] += f0.y * aa;
                    acc8[2] += f1.x * aa; acc8[3] += f1.y * aa;
                    acc8[4] += f2.x * aa; acc8[5] += f2.y * aa;
                    acc8[6] += f3.x * aa; acc8[7] += f3.y * aa;
                }
            }
#pragma unroll
            for (int i = 0; i < 8; i++)
                acc8[i] += __shfl_down_sync(0xffffffffu, acc8[i], 16);
#pragma unroll
            for (int o = 16; o; o >>= 1) {
                q0 += __shfl_xor_sync(0xffffffffu, q0, o);
                q1 += __shfl_xor_sync(0xffffffffu, q1, o);
                q2 += __shfl_xor_sync(0xffffffffu, q2, o);
                q3 += __shfl_xor_sync(0xffffffffu, q3, o);
            }
            float qh = (hh == 0) ? q0 : ((hh == 1) ? q1 : ((hh == 2) ? q2 : q3));
            float inv = 1.f / qh;
#pragma unroll
            for (int i = 0; i < 8; i++) acc8[i] *= inv;
        }
        if (hf == 0) {     // relu + fp16 pack into sA row
            uint4 u;
            unsigned* pu = reinterpret_cast<unsigned*>(&u);
#pragma unroll
            for (int p = 0; p < 4; p++) {
                float lo = fmaxf(acc8[p * 2], 0.f), hi2 = fmaxf(acc8[p * 2 + 1], 0.f);
                __half2 hp = __float22half2_rn(make_float2(lo, hi2));
                pu[p] = *reinterpret_cast<unsigned*>(&hp);
            }
            *reinterpret_cast<uint4*>(&sA[(it * 8 + w) * 136 + sub * 8]) = u;
        }
    }
    __syncthreads();   // act tile complete; s_w/s_src dead -> sB (W) may load

    gemm_core(sbuf, whichW, rb, featOut, elOut, erOut);
}

// ---------------- final aggregation + fused graph max-pool (reads A buffers) ------
__global__ void aggregate_pool_kernel() {
    __shared__ float s_w[8][4][33];
    __shared__ int   s_src[8][32];
    __shared__ float s_pool[8][128];
    int node = (blockIdx.x * blockDim.x + threadIdx.x) >> 5;
    int lane = threadIdx.x & 31;
    int w    = threadIdx.x >> 5;
    int sub  = lane & 15, hf = lane >> 4;
    int hh   = sub >> 2;

    int s0  = g_rowptr[node];
    int deg = g_rowptr[node + 1] - s0;
    float acc8[8];
#pragma unroll
    for (int i = 0; i < 8; i++) acc8[i] = 0.f;
    float q0 = 0.f, q1 = 0.f, q2 = 0.f, q3 = 0.f;

    if (deg > 0) {
        const float4* el4 = reinterpret_cast<const float4*>(g_elA);
        float4 erd = reinterpret_cast<const float4*>(g_erA)[node];
        const uint4* feat4 = reinterpret_cast<const uint4*>(g_featA);

        for (int base = 0; base < deg; base += 32) {
            int idx = base + lane;
            int s = 0;
            float w0 = 0.f, w1 = 0.f, w2 = 0.f, w3 = 0.f;
            if (idx < deg) {
                s = __ldg(&g_esrc[s0 + idx]);
                float4 ev = __ldg(&el4[s]);
                w0 = __expf(lrelu(ev.x + erd.x));
                w1 = __expf(lrelu(ev.y + erd.y));
                w2 = __expf(lrelu(ev.z + erd.z));
                w3 = __expf(lrelu(ev.w + erd.w));
                q0 += w0; q1 += w1; q2 += w2; q3 += w3;
            }
            __syncwarp();
            s_src[w][lane] = s;
            s_w[w][0][lane] = w0; s_w[w][1][lane] = w1;
            s_w[w][2][lane] = w2; s_w[w][3][lane] = w3;
            __syncwarp();
            int cnt = min(32, deg - base);
#pragma unroll 4
            for (int j = 0; j < cnt; j += 2) {
                int jj = j + hf;
                int   sj = 0;
                float aa = 0.f;
                if (jj < cnt) {
                    sj = s_src[w][jj];
                    aa = s_w[w][hh][jj];
                }
                uint4 fr = __ldg(&feat4[(size_t)sj * 16 + sub]);
                float2 f0 = __half22float2(*reinterpret_cast<__half2*>(&fr.x));
                float2 f1 = __half22float2(*reinterpret_cast<__half2*>(&fr.y));
                float2 f2 = __half22float2(*reinterpret_cast<__half2*>(&fr.z));
                float2 f3 = __half22float2(*reinterpret_cast<__half2*>(&fr.w));
                acc8[0] += f0.x * aa; acc8[1] += f0.y * aa;
                acc8[2] += f1.x * aa; acc8[3] += f1.y * aa;
                acc8[4] += f2.x * aa; acc8[5] += f2.y * aa;
                acc8[6] += f3.x * aa; acc8[7] += f3.y * aa;
            }
        }
#pragma unroll
        for (int i = 0; i < 8; i++)
            acc8[i] += __shfl_down_sync(0xffffffffu, acc8[i], 16);
#pragma unroll
        for (int o = 16; o; o >>= 1) {
            q0 += __shfl_xor_sync(0xffffffffu, q0, o);
            q1 += __shfl_xor_sync(0xffffffffu, q1, o);
            q2 += __shfl_xor_sync(0xffffffffu, q2, o);
            q3 += __shfl_xor_sync(0xffffffffu, q3, o);
        }
        float qh = (hh == 0) ? q0 : ((hh == 1) ? q1 : ((hh == 2) ? q2 : q3));
        float inv = 1.f / qh;
#pragma unroll
        for (int i = 0; i < 8; i++) acc8[i] *= inv;
    }
#pragma unroll
    for (int i = 0; i < 8; i++) acc8[i] = fmaxf(acc8[i], 0.f);

    if (hf == 0) {
#pragma unroll
        for (int i = 0; i < 8; i++) s_pool[w][sub * 8 + i] = acc8[i];
    }
    __syncthreads();
    int t = threadIdx.x;
    if (t < 128) {
        float m = s_pool[0][t];
#pragma unroll
        for (int i = 1; i < 8; i++) m = fmaxf(m, s_pool[i][t]);
        atomicMax(reinterpret_cast<int*>(&g_pooled[t]), __float_as_int(m));
    }
}

// ---------------- FC + softmax head ----------------
__global__ void head_kernel(const float* __restrict__ Wfc, const float* __restrict__ bfc,
                            float* __restrict__ out) {
    __shared__ float lg[8];
    int t = threadIdx.x;
    if (t < 8) {
        float acc = bfc[t];
        for (int k = 0; k < 128; k++) acc += g_pooled[k] * Wfc[k * 8 + t];
        lg[t] = acc;
    }
    __syncthreads();
    if (t == 0) {
        float m = lg[0];
        for (int i = 1; i < 8; i++) m = fmaxf(m, lg[i]);
        float e[8], s = 0.f;
        for (int i = 0; i < 8; i++) { e[i] = expf(lg[i] - m); s += e[i]; }
        for (int i = 0; i < 8; i++) out[i] = e[i] / s;
    }
}

// ---------------- launch ----------------
extern "C" void kernel_launch(void* const* d_in, const int* in_sizes, int n_in,
                              void* d_out, int out_size) {
    (void)in_sizes; (void)n_in; (void)out_size;
    const float* x   = (const float*)d_in[0];
    const int*   src = (const int*)d_in[1];
    const int*   dst = (const int*)d_in[2];
    const float* W1  = (const float*)d_in[3];
    const float* al1 = (const float*)d_in[4];
    const float* ar1 = (const float*)d_in[5];
    const float* W2  = (const float*)d_in[6];
    const float* al2 = (const float*)d_in[7];
    const float* ar2 = (const float*)d_in[8];
    const float* W3  = (const float*)d_in[9];
    const float* al3 = (const float*)d_in[10];
    const float* ar3 = (const float*)d_in[11];
    const float* Wfc = (const float*)d_in[12];
    const float* bfc = (const float*)d_in[13];
    float* out = (float*)d_out;

    cudaFuncSetAttribute(count_gemm1_kernel,
                         cudaFuncAttributeMaxDynamicSharedMemorySize, SMEM_GEMM);
    cudaFuncSetAttribute(fill_gemm1_kernel,
                         cudaFuncAttributeMaxDynamicSharedMemorySize, SMEM_GEMM);
    cudaFuncSetAttribute(fused_agg_gemm_kernel,
                         cudaFuncAttributeMaxDynamicSharedMemorySize, SMEM_GEMM);
    cudaFuncSetAttribute(count_gemm1_kernel,
                         cudaFuncAttributePreferredSharedMemoryCarveout, 100);
    cudaFuncSetAttribute(fill_gemm1_kernel,
                         cudaFuncAttributePreferredSharedMemoryCarveout, 100);
    cudaFuncSetAttribute(fused_agg_gemm_kernel,
                         cudaFuncAttributePreferredSharedMemoryCarveout, 100);

    prep_kernel<<<(N_NODES + 255) / 256, 256>>>(W1, W2, W3);

    // count interleaved with gemm1 half A
    count_gemm1_kernel<<<CSR_BLOCKS + GEMM_HALF_A, 256, SMEM_GEMM>>>(dst, x, al1, ar1);
    scan1_kernel<<<NBLK_SCAN, 1024>>>();
    scan3_kernel<<<(N_NODES + 255) / 256, 256>>>();
    // fill interleaved with gemm1 half B
    fill_gemm1_kernel<<<CSR_BLOCKS + GEMM_HALF_B, 256, SMEM_GEMM>>>(src, dst, x, al1, ar1);

    // agg(layer1) + gemm(layer2): A -> B
    fused_agg_gemm_kernel<<<GEMM_BLOCKS, 256, SMEM_GEMM>>>(0, 1, al2, ar2);
    // agg(layer2) + gemm(layer3): B -> A
    fused_agg_gemm_kernel<<<GEMM_BLOCKS, 256, SMEM_GEMM>>>(1, 2, al3, ar3);
    // agg(layer3) + max-pool (reads A)
    aggregate_pool_kernel<<<N_NODES / 8, 256>>>();

    head_kernel<<<1, 32>>>(Wfc, bfc, out);
}